// round 13
// baseline (speedup 1.0000x reference)
#include <cuda_runtime.h>
#include <math.h>

// Problem constants
#define BATCH 128
#define TLEN  160000

// Decomposition: warp-parallel scan, no smem, no barriers
#define TILE        128                 // samples per warp-tile (float4 per lane)
#define TILES_PER_W 10                  // tiles per warp segment
#define SEG         (TILE * TILES_PER_W)    // 1280 samples
#define WARPS_PER_CH (TLEN / SEG)       // 125
#define NWARPS      (BATCH * WARPS_PER_CH)  // 16000
#define NTHREADS    256                 // 8 warps/block
#define NBLOCKS     (NWARPS * 32 / NTHREADS) // 2000

// Biquad @ cutoff=fs/4: cos(w0)=0 => a1=0, b2=b0.
//   y[n] = f[n] - a2*y[n-2],  f[n] = b0*(x[n]+x[n-2]) + b1*x[n-1]
// Per-parity first-order chains with constant coeff c2=a2^2 = 0.0295.
// 2-step Kogge-Stone: omitted terms weighted c2^4 = 7.6e-7 (0.1% of the 1e-3 gate).
// Carries ride the rotate shuffle: lane0 receives lane31's value = next carry.

__device__ __forceinline__ void tile_step(
    float4 xv, int lane,
    float b0, float b1, float a2, float c2,
    float& xm1, float& xm2, float& yin_e, float& yin_o,
    float4& yout)
{
    const unsigned FULL = 0xFFFFFFFFu;
    const int rot = (lane + 31) & 31;

    // neighbor x via rotate: lanes>=1 get lane-1's value; lane0 slot = lane31's (next carry)
    float rz = __shfl_sync(FULL, xv.z, rot);
    float rw = __shfl_sync(FULL, xv.w, rot);
    float xa2 = (lane == 0) ? xm2 : rz;   // x[4l-2]
    float xa1 = (lane == 0) ? xm1 : rw;   // x[4l-1]
    xm2 = rz; xm1 = rw;                   // only lane0's copy matters next tile

    // FIR part f[n]
    float f0 = fmaf(b0, xv.x + xa2, b1 * xa1);
    float f1 = fmaf(b0, xv.y + xa1, b1 * xv.x);
    float f2 = fmaf(b0, xv.z + xv.x, b1 * xv.y);
    float f3 = fmaf(b0, xv.w + xv.y, b1 * xv.z);

    // per-lane combined increments for the two parity chains
    float dE = fmaf(-a2, f0, f2);   // y[4l+2] = dE + c2*y[4l-2]
    float dO = fmaf(-a2, f1, f3);
    // seed incoming state into lane 0: scan propagates it with weights c2^(l+1)
    if (lane == 0) { dE = fmaf(c2, yin_e, dE); dO = fmaf(c2, yin_o, dO); }

    // 2-step Kogge-Stone, constant coefficient (squares each step).
    // Covers distance 3; omitted weight c2^4 = 7.6e-7 -> ~1e-6 rel, decays thereafter.
    {
        float tE = __shfl_up_sync(FULL, dE, 1);
        float tO = __shfl_up_sync(FULL, dO, 1);
        if (lane >= 1) { dE = fmaf(c2, tE, dE); dO = fmaf(c2, tO, dO); }
        float m2 = c2 * c2;
        tE = __shfl_up_sync(FULL, dE, 2);
        tO = __shfl_up_sync(FULL, dO, 2);
        if (lane >= 2) { dE = fmaf(m2, tE, dE); dO = fmaf(m2, tO, dO); }
    }
    float yE2 = dE;   // y[4l+2]
    float yO3 = dO;   // y[4l+3]

    // previous y via rotate; lane0 uses carry; lane0's rotate value = next carry
    float rE = __shfl_sync(FULL, yE2, rot);
    float rO = __shfl_sync(FULL, yO3, rot);
    float yprevE = (lane == 0) ? yin_e : rE;   // y[4l-2]
    float yprevO = (lane == 0) ? yin_o : rO;   // y[4l-1]
    yin_e = rE; yin_o = rO;

    float yE0 = fmaf(-a2, yprevE, f0);  // y[4l]
    float yO1 = fmaf(-a2, yprevO, f1);  // y[4l+1]
    yout = make_float4(yE0, yO1, yE2, yO3);
}

__global__ void __launch_bounds__(NTHREADS, 6)   // cap regs ~42 -> 6 blocks/SM
biquad_kernel(const float* __restrict__ x, float* __restrict__ y,
              float b0, float b1, float a2)
{
    const int gtid = blockIdx.x * NTHREADS + threadIdx.x;
    const int w    = gtid >> 5;
    const int lane = gtid & 31;
    const int ch   = w / WARPS_PER_CH;
    const int seg  = w % WARPS_PER_CH;
    const long base = (long)ch * TLEN + (long)seg * SEG;

    const float4* __restrict__ xin = (const float4*)(x + base);
    float4* __restrict__       yo4 = (float4*)(y + base);

    const float c2 = a2 * a2;
    float xm1 = 0.0f, xm2 = 0.0f, yin_e = 0.0f, yin_o = 0.0f;

    // Warmup tile for mid-channel segments (state decay over 128 samples -> exact in fp32).
    // Channel-start segments keep true zero ICs (exact).
    if (seg > 0) {
        float4 xw = __ldcs(&xin[-32 + lane]);
        float4 dump;
        tile_step(xw, lane, b0, b1, a2, c2, xm1, xm2, yin_e, yin_o, dump);
    }

    // Main tiles, prefetch depth 2
    float4 xa = __ldcs(&xin[lane]);
    float4 xb = __ldcs(&xin[32 + lane]);
    #pragma unroll
    for (int t = 0; t < TILES_PER_W; ++t) {
        float4 xn;
        if (t + 2 < TILES_PER_W) xn = __ldcs(&xin[(t + 2) * 32 + lane]);
        float4 yo;
        tile_step(xa, lane, b0, b1, a2, c2, xm1, xm2, yin_e, yin_o, yo);
        __stcs(&yo4[t * 32 + lane], yo);
        xa = xb; xb = xn;
    }
}

extern "C" void kernel_launch(void* const* d_in, const int* in_sizes, int n_in,
                              void* d_out, int out_size)
{
    const float* x = (const float*)d_in[0];
    float* y = (float*)d_out;

    // torchaudio lowpass_biquad coefficients (double math, then float32)
    const double PI = 3.14159265358979323846;
    double w0    = 2.0 * PI * 8000.0 / 32000.0;
    double alpha = sin(w0) / (2.0 * 0.707);
    double cw    = cos(w0);           // ~6e-17: a1 term exactly negligible
    double b0d = (1.0 - cw) / 2.0;
    double b1d = 1.0 - cw;
    double a0d = 1.0 + alpha;
    double a2d = 1.0 - alpha;
    float b0 = (float)(b0d / a0d);
    float b1 = (float)(b1d / a0d);
    float a2 = (float)(a2d / a0d);

    biquad_kernel<<<NBLOCKS, NTHREADS>>>(x, y, b0, b1, a2);
}

// round 14
// speedup vs baseline: 1.0010x; 1.0010x over previous
#include <cuda_runtime.h>
#include <math.h>

// Problem constants
#define BATCH 128
#define TLEN  160000

// Decomposition: warp-parallel scan, no smem, no barriers
#define TILE        128                 // samples per warp-tile (float4 per lane)
#define TILES_PER_W 10                  // tiles per warp segment
#define SEG         (TILE * TILES_PER_W)    // 1280 samples
#define WARPS_PER_CH (TLEN / SEG)       // 125
#define NWARPS      (BATCH * WARPS_PER_CH)  // 16000
#define NTHREADS    128                 // 4 warps/block (fine scheduling granules)
#define NBLOCKS     (NWARPS * 32 / NTHREADS) // 4000
#define PF          4                   // prefetch depth: cover a full mem round trip

// Biquad @ cutoff=fs/4: cos(w0)=0 => a1=0, b2=b0.
//   y[n] = f[n] - a2*y[n-2],  f[n] = b0*(x[n]+x[n-2]) + b1*x[n-1]
// Per-parity first-order chains with constant coeff c2=a2^2 = 0.0295.
// 2-step Kogge-Stone: omitted terms weighted c2^4 = 7.6e-7 (0.1% of the 1e-3 gate).
// Carries ride the rotate shuffle: lane0 receives lane31's value = next carry.

__device__ __forceinline__ void tile_step(
    float4 xv, int lane,
    float b0, float b1, float a2, float c2,
    float& xm1, float& xm2, float& yin_e, float& yin_o,
    float4& yout)
{
    const unsigned FULL = 0xFFFFFFFFu;
    const int rot = (lane + 31) & 31;

    // neighbor x via rotate: lanes>=1 get lane-1's value; lane0 slot = lane31's (next carry)
    float rz = __shfl_sync(FULL, xv.z, rot);
    float rw = __shfl_sync(FULL, xv.w, rot);
    float xa2 = (lane == 0) ? xm2 : rz;   // x[4l-2]
    float xa1 = (lane == 0) ? xm1 : rw;   // x[4l-1]
    xm2 = rz; xm1 = rw;                   // only lane0's copy matters next tile

    // FIR part f[n]
    float f0 = fmaf(b0, xv.x + xa2, b1 * xa1);
    float f1 = fmaf(b0, xv.y + xa1, b1 * xv.x);
    float f2 = fmaf(b0, xv.z + xv.x, b1 * xv.y);
    float f3 = fmaf(b0, xv.w + xv.y, b1 * xv.z);

    // per-lane combined increments for the two parity chains
    float dE = fmaf(-a2, f0, f2);   // y[4l+2] = dE + c2*y[4l-2]
    float dO = fmaf(-a2, f1, f3);
    // seed incoming state into lane 0: scan propagates it with weights c2^(l+1)
    if (lane == 0) { dE = fmaf(c2, yin_e, dE); dO = fmaf(c2, yin_o, dO); }

    // 2-step Kogge-Stone, constant coefficient (squares each step).
    // Covers distance 3; omitted weight c2^4 = 7.6e-7 -> ~1e-6 rel, decays thereafter.
    {
        float tE = __shfl_up_sync(FULL, dE, 1);
        float tO = __shfl_up_sync(FULL, dO, 1);
        if (lane >= 1) { dE = fmaf(c2, tE, dE); dO = fmaf(c2, tO, dO); }
        float m2 = c2 * c2;
        tE = __shfl_up_sync(FULL, dE, 2);
        tO = __shfl_up_sync(FULL, dO, 2);
        if (lane >= 2) { dE = fmaf(m2, tE, dE); dO = fmaf(m2, tO, dO); }
    }
    float yE2 = dE;   // y[4l+2]
    float yO3 = dO;   // y[4l+3]

    // previous y via rotate; lane0 uses carry; lane0's rotate value = next carry
    float rE = __shfl_sync(FULL, yE2, rot);
    float rO = __shfl_sync(FULL, yO3, rot);
    float yprevE = (lane == 0) ? yin_e : rE;   // y[4l-2]
    float yprevO = (lane == 0) ? yin_o : rO;   // y[4l-1]
    yin_e = rE; yin_o = rO;

    float yE0 = fmaf(-a2, yprevE, f0);  // y[4l]
    float yO1 = fmaf(-a2, yprevO, f1);  // y[4l+1]
    yout = make_float4(yE0, yO1, yE2, yO3);
}

__global__ void __launch_bounds__(NTHREADS, 10)   // reg cap ~50 -> 10 blocks/SM
biquad_kernel(const float* __restrict__ x, float* __restrict__ y,
              float b0, float b1, float a2)
{
    const int gtid = blockIdx.x * NTHREADS + threadIdx.x;
    const int w    = gtid >> 5;
    const int lane = gtid & 31;
    const int ch   = w / WARPS_PER_CH;
    const int seg  = w % WARPS_PER_CH;
    const long base = (long)ch * TLEN + (long)seg * SEG;

    const float4* __restrict__ xin = (const float4*)(x + base);
    float4* __restrict__       yo4 = (float4*)(y + base);

    const float c2 = a2 * a2;
    float xm1 = 0.0f, xm2 = 0.0f, yin_e = 0.0f, yin_o = 0.0f;

    // Front-batch the prefetch ring BEFORE the warmup tile:
    // 4-5 independent LDGs in flight while warmup computes.
    float4 xbuf[PF];
    #pragma unroll
    for (int i = 0; i < PF; ++i)
        xbuf[i] = __ldcs(&xin[i * 32 + lane]);

    // Warmup tile for mid-channel segments (state decay over 128 samples -> exact in fp32).
    // Channel-start segments keep true zero ICs (exact).
    if (seg > 0) {
        float4 xw = __ldcs(&xin[-32 + lane]);
        float4 dump;
        tile_step(xw, lane, b0, b1, a2, c2, xm1, xm2, yin_e, yin_o, dump);
    }

    // Main tiles, prefetch ring depth 4
    #pragma unroll
    for (int t = 0; t < TILES_PER_W; ++t) {
        float4 xc = xbuf[t % PF];
        if (t + PF < TILES_PER_W)
            xbuf[t % PF] = __ldcs(&xin[(t + PF) * 32 + lane]);
        float4 yo;
        tile_step(xc, lane, b0, b1, a2, c2, xm1, xm2, yin_e, yin_o, yo);
        __stcs(&yo4[t * 32 + lane], yo);
    }
}

extern "C" void kernel_launch(void* const* d_in, const int* in_sizes, int n_in,
                              void* d_out, int out_size)
{
    const float* x = (const float*)d_in[0];
    float* y = (float*)d_out;

    // torchaudio lowpass_biquad coefficients (double math, then float32)
    const double PI = 3.14159265358979323846;
    double w0    = 2.0 * PI * 8000.0 / 32000.0;
    double alpha = sin(w0) / (2.0 * 0.707);
    double cw    = cos(w0);           // ~6e-17: a1 term exactly negligible
    double b0d = (1.0 - cw) / 2.0;
    double b1d = 1.0 - cw;
    double a0d = 1.0 + alpha;
    double a2d = 1.0 - alpha;
    float b0 = (float)(b0d / a0d);
    float b1 = (float)(b1d / a0d);
    float a2 = (float)(a2d / a0d);

    biquad_kernel<<<NBLOCKS, NTHREADS>>>(x, y, b0, b1, a2);
}

// round 15
// speedup vs baseline: 1.0021x; 1.0010x over previous
#include <cuda_runtime.h>
#include <math.h>

// Problem constants
#define BATCH 128
#define TLEN  160000

// Decomposition: warp-parallel scan, 8 samples/lane, no smem, no barriers
#define TILE        256                 // samples per warp-tile (2x float4 per lane)
#define TILES_PER_W 5                   // tiles per warp segment
#define SEG         (TILE * TILES_PER_W)    // 1280 samples
#define WARPS_PER_CH (TLEN / SEG)       // 125
#define NWARPS      (BATCH * WARPS_PER_CH)  // 16000
#define NTHREADS    128                 // 4 warps/block
#define NBLOCKS     (NWARPS * 32 / NTHREADS) // 4000
#define PF          2                   // prefetch depth (tiles) = 4 float4 in flight

// Biquad @ cutoff=fs/4: cos(w0)=0 => a1=0, b2=b0.
//   y[n] = f[n] - a2*y[n-2],  f[n] = b0*(x[n]+x[n-2]) + b1*x[n-1]
// Lane owns 8 contiguous samples -> per-parity 4-step chain -> lane-hop
// coefficient m4 = a2^4 = 8.7e-4. ONE Kogge-Stone step suffices
// (omitted weight m4^2 = 7.5e-7, far under the 1e-3 gate).
// Carries ride the rotate shuffle: lane0 receives lane31's value = next carry.

__device__ __forceinline__ void tile_step(
    float4 xA, float4 xB, int lane,
    float b0, float b1, float a2, float m4,
    float& xm1, float& xm2, float& yin_e, float& yin_o,
    float4& yoA, float4& yoB)
{
    const unsigned FULL = 0xFFFFFFFFu;
    const int rot = (lane + 31) & 31;

    // neighbor x via rotate: lanes>=1 get lane-1's x[8l-2],x[8l-1]; lane0 slot = next carry
    float rz = __shfl_sync(FULL, xB.z, rot);
    float rw = __shfl_sync(FULL, xB.w, rot);
    float xa2 = (lane == 0) ? xm2 : rz;
    float xa1 = (lane == 0) ? xm1 : rw;
    xm2 = rz; xm1 = rw;                 // only lane0's copy matters next tile

    // FIR part f[n], n = 8l..8l+7
    float f0 = fmaf(b0, xA.x + xa2,  b1 * xa1);
    float f1 = fmaf(b0, xA.y + xa1,  b1 * xA.x);
    float f2 = fmaf(b0, xA.z + xA.x, b1 * xA.y);
    float f3 = fmaf(b0, xA.w + xA.y, b1 * xA.z);
    float f4 = fmaf(b0, xB.x + xA.z, b1 * xA.w);
    float f5 = fmaf(b0, xB.y + xA.w, b1 * xB.x);
    float f6 = fmaf(b0, xB.z + xB.x, b1 * xB.y);
    float f7 = fmaf(b0, xB.w + xB.y, b1 * xB.z);

    // Lane-local increments (Horner): dE = f6 - a2 f4 + a2^2 f2 - a2^3 f0
    float tE = fmaf(-a2, f0, f2);  tE = fmaf(-a2, tE, f4);  float dE = fmaf(-a2, tE, f6);
    float tO = fmaf(-a2, f1, f3);  tO = fmaf(-a2, tO, f5);  float dO = fmaf(-a2, tO, f7);

    // seed incoming state into lane 0 (scan gives lane1 the m4^2 term; lanes>=2 omitted ~6e-10)
    if (lane == 0) { dE = fmaf(m4, yin_e, dE); dO = fmaf(m4, yin_o, dO); }

    // 1-step scan, coefficient m4
    {
        float sE = __shfl_up_sync(FULL, dE, 1);
        float sO = __shfl_up_sync(FULL, dO, 1);
        if (lane >= 1) { dE = fmaf(m4, sE, dE); dO = fmaf(m4, sO, dO); }
    }
    // dE = y[8l+6], dO = y[8l+7]

    // previous y via rotate; lane0 uses carry; lane0's rotate slot = next carry
    float rE = __shfl_sync(FULL, dE, rot);
    float rO = __shfl_sync(FULL, dO, rot);
    float ypE = (lane == 0) ? yin_e : rE;   // y[8l-2]
    float ypO = (lane == 0) ? yin_o : rO;   // y[8l-1]
    yin_e = rE; yin_o = rO;

    // within-lane outputs, exact given (ypE, ypO)
    float y0 = fmaf(-a2, ypE, f0);
    float y1 = fmaf(-a2, ypO, f1);
    float y2 = fmaf(-a2, y0,  f2);
    float y3 = fmaf(-a2, y1,  f3);
    float y4 = fmaf(-a2, y2,  f4);
    float y5 = fmaf(-a2, y3,  f5);
    float y6 = fmaf(-a2, y4,  f6);
    float y7 = fmaf(-a2, y5,  f7);
    yoA = make_float4(y0, y1, y2, y3);
    yoB = make_float4(y4, y5, y6, y7);
}

__global__ void __launch_bounds__(NTHREADS, 8)   // reg cap 64
biquad_kernel(const float* __restrict__ x, float* __restrict__ y,
              float b0, float b1, float a2)
{
    const int gtid = blockIdx.x * NTHREADS + threadIdx.x;
    const int w    = gtid >> 5;
    const int lane = gtid & 31;
    const int ch   = w / WARPS_PER_CH;
    const int seg  = w % WARPS_PER_CH;
    const long base = (long)ch * TLEN + (long)seg * SEG;

    const float4* __restrict__ xin = (const float4*)(x + base);
    float4* __restrict__       yo4 = (float4*)(y + base);

    const float c2 = a2 * a2;
    const float m4 = c2 * c2;           // a2^4 = 8.7e-4
    float xm1 = 0.0f, xm2 = 0.0f, yin_e = 0.0f, yin_o = 0.0f;

    // Front-batch the prefetch ring (independent LDGs in flight during warmup)
    float4 bufA[PF], bufB[PF];
    #pragma unroll
    for (int i = 0; i < PF; ++i) {
        bufA[i] = __ldcs(&xin[i * 64 + 2 * lane]);
        bufB[i] = __ldcs(&xin[i * 64 + 2 * lane + 1]);
    }

    // Warmup tile (256 samples) for mid-channel segments: state decays to sub-fp32.
    // Channel-start segments keep true zero ICs (exact).
    if (seg > 0) {
        float4 wA = __ldcs(&xin[-64 + 2 * lane]);
        float4 wB = __ldcs(&xin[-64 + 2 * lane + 1]);
        float4 dA, dB;
        tile_step(wA, wB, lane, b0, b1, a2, m4, xm1, xm2, yin_e, yin_o, dA, dB);
    }

    // Main tiles, prefetch ring depth 2
    #pragma unroll
    for (int t = 0; t < TILES_PER_W; ++t) {
        float4 xA = bufA[t % PF];
        float4 xB = bufB[t % PF];
        if (t + PF < TILES_PER_W) {
            bufA[t % PF] = __ldcs(&xin[(t + PF) * 64 + 2 * lane]);
            bufB[t % PF] = __ldcs(&xin[(t + PF) * 64 + 2 * lane + 1]);
        }
        float4 yoA, yoB;
        tile_step(xA, xB, lane, b0, b1, a2, m4, xm1, xm2, yin_e, yin_o, yoA, yoB);
        __stcs(&yo4[t * 64 + 2 * lane],     yoA);
        __stcs(&yo4[t * 64 + 2 * lane + 1], yoB);
    }
}

extern "C" void kernel_launch(void* const* d_in, const int* in_sizes, int n_in,
                              void* d_out, int out_size)
{
    const float* x = (const float*)d_in[0];
    float* y = (float*)d_out;

    // torchaudio lowpass_biquad coefficients (double math, then float32)
    const double PI = 3.14159265358979323846;
    double w0    = 2.0 * PI * 8000.0 / 32000.0;
    double alpha = sin(w0) / (2.0 * 0.707);
    double cw    = cos(w0);           // ~6e-17: a1 term exactly negligible
    double b0d = (1.0 - cw) / 2.0;
    double b1d = 1.0 - cw;
    double a0d = 1.0 + alpha;
    double a2d = 1.0 - alpha;
    float b0 = (float)(b0d / a0d);
    float b1 = (float)(b1d / a0d);
    float a2 = (float)(a2d / a0d);

    biquad_kernel<<<NBLOCKS, NTHREADS>>>(x, y, b0, b1, a2);
}